// round 9
// baseline (speedup 1.0000x reference)
#include <cuda_runtime.h>
#include <math.h>

#define N_NODES 100000
#define N_EDGES 1000000
#define D_NODE 64
#define D_EDGE 16
#define NUM_PAR 80
#define HIDDEN 160

#define NODE_BLOCKS 592
#define NODE_THREADS 512          // 16 warps; 2 nodes per warp per iteration

#define EDGE_THREADS 256
#define EDGE_EPT 8                // edges per thread (block-strided)
#define EDGE_BLOCKS ((N_EDGES + EDGE_THREADS * EDGE_EPT - 1) / (EDGE_THREADS * EDGE_EPT))

// Scratch (allocation-free rule).
__device__ float g_p[N_NODES];
__device__ float g_w16[D_EDGE];   // collapsed w[64:80], written by node_kernel blk 0
__device__ float g_c;             // collapsed bias,    written by node_kernel blk 0

// Warp-cooperative collapsed weight for one row r of W1:
//   w[r] = sum_j W1[r,j] * W2[j], lane-parallel over j (5 strides of 32).
__device__ __forceinline__ float collapse_row(const float* __restrict__ W1,
                                              const float* __restrict__ w2reg,
                                              int r, int lane) {
    const float* row = W1 + r * HIDDEN;
    float s = 0.f;
    #pragma unroll
    for (int k = 0; k < 5; k++)
        s = fmaf(__ldg(row + lane + 32 * k), w2reg[k], s);
    #pragma unroll
    for (int o = 16; o > 0; o >>= 1)
        s += __shfl_xor_sync(0xFFFFFFFFu, s, o);
    return s;   // valid in all lanes
}

// ---------------------------------------------------------------------------
// Kernel A: node projections p[n] = dot(x[n], w[0:64]).
// Warps 0-7: recompute w[0:64] per block (L2-resident after wave 1).
// Block 0, warps 8-15: also produce w[64:80] and c for the edge kernel
// (visible at next launch; removes the edge prologue).
// Main loop: warp handles 2 nodes/iter; lane loads one float4 (512B/warp,
// coalesced), 16-lane shuffle-tree reduction.
// ---------------------------------------------------------------------------
__global__ __launch_bounds__(NODE_THREADS)
void node_kernel(const float* __restrict__ x,
                 const float* __restrict__ W1,
                 const float* __restrict__ b1,
                 const float* __restrict__ W2,
                 const float* __restrict__ b2) {
    __shared__ float sw[D_NODE];
    int t = threadIdx.x;
    int warp = t >> 5;
    int lane = t & 31;

    if (warp < 8) {
        float w2[5];
        #pragma unroll
        for (int k = 0; k < 5; k++) w2[k] = __ldg(W2 + lane + 32 * k);
        #pragma unroll
        for (int rr = 0; rr < 8; rr++) {
            int r = warp * 8 + rr;
            float s = collapse_row(W1, w2, r, lane);
            if (lane == 0) sw[r] = s;
        }
    } else if (blockIdx.x == 0) {
        float w2[5];
        #pragma unroll
        for (int k = 0; k < 5; k++) w2[k] = __ldg(W2 + lane + 32 * k);
        int i = warp - 8;
        #pragma unroll
        for (int rr = 0; rr < 2; rr++) {
            float s = collapse_row(W1, w2, D_NODE + 2 * i + rr, lane);
            if (lane == 0) g_w16[2 * i + rr] = s;
        }
        if (warp == 8) {   // c = b1 . W2 + b2
            float s = 0.f;
            #pragma unroll
            for (int k = 0; k < 5; k++)
                s = fmaf(__ldg(b1 + lane + 32 * k), w2[k], s);
            #pragma unroll
            for (int o = 16; o > 0; o >>= 1)
                s += __shfl_xor_sync(0xFFFFFFFFu, s, o);
            if (lane == 0) g_c = s + __ldg(b2);
        }
    }
    __syncthreads();

    int half = lane >> 4;        // which of the warp's 2 nodes
    int q    = lane & 15;        // float4 slot within the node row
    float w0 = sw[q * 4 + 0];
    float w1 = sw[q * 4 + 1];
    float w2r = sw[q * 4 + 2];
    float w3 = sw[q * 4 + 3];

    const float4* x4 = (const float4*)x;
    const int stride = NODE_BLOCKS * (NODE_THREADS / 32) * 2;

    for (int node = blockIdx.x * ((NODE_THREADS / 32) * 2) + warp * 2 + half;
         node < N_NODES; node += stride) {
        float4 v = __ldg(x4 + (size_t)node * 16 + q);
        float s = fmaf(v.x, w0, fmaf(v.y, w1, fmaf(v.z, w2r, v.w * w3)));
        #pragma unroll
        for (int o = 8; o > 0; o >>= 1)
            s += __shfl_xor_sync(0xFFFFFFFFu, s, o);
        if (q == 0) g_p[node] = s;
    }
}

// ---------------------------------------------------------------------------
// Kernel B: per-edge  z = p[src] + p[dst] + ea[e].w[64:80] + c;  sigmoid(z).
// Thread-private, deep-MLP layout (R7 skeleton):
//   phase 1: 16 coalesced index loads (low-word reads work for int32 and
//            int64<2^31 via stride mult)
//   phase 2: 16 scattered p-gathers back-to-back (the only random traffic;
//            p is 400KB, L2-resident)
//   phase 3: per-edge float4 streaming, software-pipelined one edge ahead;
//            weights read from smem (broadcast, conflict-free), z as 4-way
//            FMA tree. ~50 regs -> 5 blocks/SM (40 warps).
// ---------------------------------------------------------------------------
__global__ __launch_bounds__(EDGE_THREADS, 5)
void edge_kernel(const void* __restrict__ ei_raw,
                 const float* __restrict__ ea,
                 float* __restrict__ out) {
    __shared__ float sw[D_EDGE];
    __shared__ float sc;
    __shared__ int   smult;
    int t = threadIdx.x;
    int lane = t & 31;

    if (t < 32) {
        // Dtype probe: 32 entries as int64 all in [0,N_NODES) <=> truly int64
        // (int32 data would need 32 zero hi-words: P ~ 1e-160).
        const long long* ei64 = (const long long*)ei_raw;
        long long v = __ldg(ei64 + lane);
        unsigned b = __ballot_sync(0xFFFFFFFFu, v >= 0 && v < N_NODES);
        if (lane == 0) smult = (b == 0xFFFFFFFFu) ? 2 : 1;
    } else if (t < 64) {
        int i = t - 32;
        if (i < D_EDGE) sw[i] = g_w16[i];
        if (i == D_EDGE) sc = g_c;
    }
    __syncthreads();

    const float cc = sc;
    const int mult = smult;
    const int* eidx = (const int*)ei_raw;   // low 4B hold the value (LE)

    const int base = blockIdx.x * (EDGE_THREADS * EDGE_EPT) + t;

    // Phase 1: all 16 index loads (coalesced).
    int srcs[EDGE_EPT], dsts[EDGE_EPT];
    #pragma unroll
    for (int k = 0; k < EDGE_EPT; k++) {
        int e  = base + k * EDGE_THREADS;
        int ec = e < N_EDGES ? e : (N_EDGES - 1);
        srcs[k] = __ldg(eidx + (size_t)mult * ec);
        dsts[k] = __ldg(eidx + (size_t)mult * ((size_t)N_EDGES + ec));
    }

    // Phase 2: all 16 scattered p-gathers issued back-to-back.
    float ps[EDGE_EPT];
    #pragma unroll
    for (int k = 0; k < EDGE_EPT; k++)
        ps[k] = g_p[srcs[k]] + g_p[dsts[k]];

    // Phase 3: per-edge streaming, pipelined one edge ahead.
    float4 c0, c1, c2, c3;
    {
        int e = base < N_EDGES ? base : (N_EDGES - 1);
        const float4* A = (const float4*)(ea + (size_t)e * D_EDGE);
        c0 = __ldg(A + 0); c1 = __ldg(A + 1); c2 = __ldg(A + 2); c3 = __ldg(A + 3);
    }

    #pragma unroll
    for (int k = 0; k < EDGE_EPT; k++) {
        float4 n0, n1, n2, n3;
        if (k + 1 < EDGE_EPT) {
            int e  = base + (k + 1) * EDGE_THREADS;
            int ec = e < N_EDGES ? e : (N_EDGES - 1);
            const float4* A = (const float4*)(ea + (size_t)ec * D_EDGE);
            n0 = __ldg(A + 0); n1 = __ldg(A + 1); n2 = __ldg(A + 2); n3 = __ldg(A + 3);
        }

        // 4-way FMA tree (short dependency chains).
        float z0 = fmaf(c0.x, sw[0],  fmaf(c0.y, sw[1],  fmaf(c0.z, sw[2],  c0.w * sw[3])));
        float z1 = fmaf(c1.x, sw[4],  fmaf(c1.y, sw[5],  fmaf(c1.z, sw[6],  c1.w * sw[7])));
        float z2 = fmaf(c2.x, sw[8],  fmaf(c2.y, sw[9],  fmaf(c2.z, sw[10], c2.w * sw[11])));
        float z3 = fmaf(c3.x, sw[12], fmaf(c3.y, sw[13], fmaf(c3.z, sw[14], c3.w * sw[15])));
        float z = (ps[k] + cc) + ((z0 + z1) + (z2 + z3));

        int e = base + k * EDGE_THREADS;
        if (e < N_EDGES)
            out[e] = 1.0f / (1.0f + __expf(-z));

        c0 = n0; c1 = n1; c2 = n2; c3 = n3;
    }
}

extern "C" void kernel_launch(void* const* d_in, const int* in_sizes, int n_in,
                              void* d_out, int out_size) {
    // metadata order: x, edge_index, edge_attr, W1, b1, W2, b2
    const float* x  = (const float*)d_in[0];
    const void*  ei = d_in[1];
    const float* ea = (const float*)d_in[2];
    const float* W1 = (const float*)d_in[3];
    const float* b1 = (const float*)d_in[4];
    const float* W2 = (const float*)d_in[5];
    const float* b2 = (const float*)d_in[6];
    float* out = (float*)d_out;

    node_kernel<<<NODE_BLOCKS, NODE_THREADS>>>(x, W1, b1, W2, b2);
    edge_kernel<<<EDGE_BLOCKS, EDGE_THREADS>>>(ei, ea, out);
}

// round 10
// speedup vs baseline: 1.1952x; 1.1952x over previous
#include <cuda_runtime.h>
#include <math.h>

#define N_NODES 100000
#define N_EDGES 1000000
#define D_NODE 64
#define D_EDGE 16
#define NUM_PAR 80
#define HIDDEN 160

#define NBLOCKS 592               // 148 SMs x 4 blocks, all co-resident
#define NTHREADS 256              // 8 warps
#define EPT 7                     // edges per thread: 592*256*7 = 1,060,864 >= 1e6

// Scratch (allocation-free rule).
__device__ float g_p[N_NODES];
__device__ int   g_cnt;           // barrier arrivals (self-resetting)
__device__ volatile int g_flag;   // barrier generation (monotone across replays)

// Warp-cooperative collapsed weight for one row r of W1:
//   w[r] = sum_j W1[r,j] * W2[j], lane-parallel over j (5 strides of 32).
__device__ __forceinline__ float collapse_row(const float* __restrict__ W1,
                                              const float* __restrict__ w2reg,
                                              int r, int lane) {
    const float* row = W1 + r * HIDDEN;
    float s = 0.f;
    #pragma unroll
    for (int k = 0; k < 5; k++)
        s = fmaf(__ldg(row + lane + 32 * k), w2reg[k], s);
    #pragma unroll
    for (int o = 16; o > 0; o >>= 1)
        s += __shfl_xor_sync(0xFFFFFFFFu, s, o);
    return s;   // valid in all lanes
}

// ---------------------------------------------------------------------------
// Fused persistent kernel.
//   Stage 0: per-block weight collapse (W1/W2 L2-resident after wave 1):
//            warp w -> rows 10w..10w+9 of w[0:80]; warp 7 also bias c.
//   Stage 1: node projections p[n] = x[n].w[0:64]  (warp: 2 nodes/iter,
//            lane loads float4, 16-lane shuffle tree).
//   Stage 2 (pre-barrier, independent of p): this thread's 7 edges:
//            indices (coalesced low-word loads; int32/int64 via stride mult)
//            and q[k] = ea[e].w[64:80] + c  (streams 68MB, overlaps
//            stragglers' node work across SMs).
//   Barrier: sense-reversing grid barrier (all blocks resident by design).
//   Stage 3: 14 scattered p-gathers (L2-resident 400KB), out = sigmoid(ps+q).
// ---------------------------------------------------------------------------
__global__ __launch_bounds__(NTHREADS, 4)
void fused_kernel(const float* __restrict__ x,
                  const void*  __restrict__ ei_raw,
                  const float* __restrict__ ea,
                  const float* __restrict__ W1,
                  const float* __restrict__ b1,
                  const float* __restrict__ W2,
                  const float* __restrict__ b2,
                  float* __restrict__ out) {
    __shared__ float sw[NUM_PAR];
    __shared__ float sc;
    __shared__ int   smult;
    int t = threadIdx.x;
    int warp = t >> 5;
    int lane = t & 31;

    // ---- Stage 0: weight collapse (all 8 warps; 10 rows each) ----
    {
        float w2[5];
        #pragma unroll
        for (int k = 0; k < 5; k++) w2[k] = __ldg(W2 + lane + 32 * k);
        #pragma unroll
        for (int rr = 0; rr < 10; rr++) {
            int r = warp * 10 + rr;
            float s = collapse_row(W1, w2, r, lane);
            if (lane == 0) sw[r] = s;
        }
        if (warp == 7) {   // c = b1 . W2 + b2
            float s = 0.f;
            #pragma unroll
            for (int k = 0; k < 5; k++)
                s = fmaf(__ldg(b1 + lane + 32 * k), w2[k], s);
            #pragma unroll
            for (int o = 16; o > 0; o >>= 1)
                s += __shfl_xor_sync(0xFFFFFFFFu, s, o);
            if (lane == 0) sc = s + __ldg(b2);
        }
        if (warp == 0) {
            // Dtype probe: 32 entries as int64 all in [0,N_NODES) <=> int64
            // (int32 data would need 32 zero hi-words: P ~ 1e-160).
            const long long* ei64 = (const long long*)ei_raw;
            long long v = __ldg(ei64 + lane);
            unsigned b = __ballot_sync(0xFFFFFFFFu, v >= 0 && v < N_NODES);
            if (lane == 0) smult = (b == 0xFFFFFFFFu) ? 2 : 1;
        }
    }
    __syncthreads();

    // ---- Stage 1: node projections ----
    {
        int half = lane >> 4;
        int q    = lane & 15;
        float w0 = sw[q * 4 + 0];
        float w1 = sw[q * 4 + 1];
        float w2r = sw[q * 4 + 2];
        float w3 = sw[q * 4 + 3];

        const float4* x4 = (const float4*)x;
        const int stride = NBLOCKS * 8 * 2;

        for (int node = blockIdx.x * 16 + warp * 2 + half;
             node < N_NODES; node += stride) {
            float4 v = __ldg(x4 + (size_t)node * 16 + q);
            float s = fmaf(v.x, w0, fmaf(v.y, w1, fmaf(v.z, w2r, v.w * w3)));
            #pragma unroll
            for (int o = 8; o > 0; o >>= 1)
                s += __shfl_xor_sync(0xFFFFFFFFu, s, o);
            if (q == 0) g_p[node] = s;
        }
    }

    // ---- Stage 2 (pre-barrier): indices + q = ea.w + c ----
    const int mult = smult;
    const float cc = sc;
    const int* eidx = (const int*)ei_raw;   // low 4B hold the value (LE)
    const int base = blockIdx.x * (NTHREADS * EPT) + t;

    int srcs[EPT], dsts[EPT];
    #pragma unroll
    for (int k = 0; k < EPT; k++) {
        int e  = base + k * NTHREADS;
        int ec = e < N_EDGES ? e : (N_EDGES - 1);
        srcs[k] = __ldg(eidx + (size_t)mult * ec);
        dsts[k] = __ldg(eidx + (size_t)mult * ((size_t)N_EDGES + ec));
    }

    float q[EPT];
    // Pipeline ea loads one edge ahead.
    float4 c0, c1, c2, c3;
    {
        int e = base < N_EDGES ? base : (N_EDGES - 1);
        const float4* A = (const float4*)(ea + (size_t)e * D_EDGE);
        c0 = __ldg(A + 0); c1 = __ldg(A + 1); c2 = __ldg(A + 2); c3 = __ldg(A + 3);
    }
    #pragma unroll
    for (int k = 0; k < EPT; k++) {
        float4 n0, n1, n2, n3;
        if (k + 1 < EPT) {
            int e  = base + (k + 1) * NTHREADS;
            int ec = e < N_EDGES ? e : (N_EDGES - 1);
            const float4* A = (const float4*)(ea + (size_t)ec * D_EDGE);
            n0 = __ldg(A + 0); n1 = __ldg(A + 1); n2 = __ldg(A + 2); n3 = __ldg(A + 3);
        }
        float z0 = fmaf(c0.x, sw[64], fmaf(c0.y, sw[65], fmaf(c0.z, sw[66], c0.w * sw[67])));
        float z1 = fmaf(c1.x, sw[68], fmaf(c1.y, sw[69], fmaf(c1.z, sw[70], c1.w * sw[71])));
        float z2 = fmaf(c2.x, sw[72], fmaf(c2.y, sw[73], fmaf(c2.z, sw[74], c2.w * sw[75])));
        float z3 = fmaf(c3.x, sw[76], fmaf(c3.y, sw[77], fmaf(c3.z, sw[78], c3.w * sw[79])));
        q[k] = cc + ((z0 + z1) + (z2 + z3));
        c0 = n0; c1 = n1; c2 = n2; c3 = n3;
    }

    // ---- Grid barrier (sense-reversing; all blocks resident) ----
    __syncthreads();
    if (t == 0) {
        int gen = g_flag;                    // same value in all blocks:
        __threadfence();                     // flag only moves after all arrive
        int a = atomicAdd(&g_cnt, 1);
        if (a == NBLOCKS - 1) {
            g_cnt = 0;                       // self-reset for next replay
            __threadfence();
            g_flag = gen + 1;                // release
        } else {
            while (g_flag == gen) { }        // spin (volatile)
        }
        __threadfence();
    }
    __syncthreads();

    // ---- Stage 3: scattered gathers + finish ----
    float ps[EPT];
    #pragma unroll
    for (int k = 0; k < EPT; k++)
        ps[k] = g_p[srcs[k]] + g_p[dsts[k]];

    #pragma unroll
    for (int k = 0; k < EPT; k++) {
        int e = base + k * NTHREADS;
        if (e < N_EDGES) {
            float z = ps[k] + q[k];
            out[e] = 1.0f / (1.0f + __expf(-z));
        }
    }
}

extern "C" void kernel_launch(void* const* d_in, const int* in_sizes, int n_in,
                              void* d_out, int out_size) {
    // metadata order: x, edge_index, edge_attr, W1, b1, W2, b2
    const float* x  = (const float*)d_in[0];
    const void*  ei = d_in[1];
    const float* ea = (const float*)d_in[2];
    const float* W1 = (const float*)d_in[3];
    const float* b1 = (const float*)d_in[4];
    const float* W2 = (const float*)d_in[5];
    const float* b2 = (const float*)d_in[6];
    float* out = (float*)d_out;

    fused_kernel<<<NBLOCKS, NTHREADS>>>(x, ei, ea, W1, b1, W2, b2, out);
}